// round 6
// baseline (speedup 1.0000x reference)
#include <cuda_runtime.h>
#include <cuda_bf16.h>
#include <cstdint>

#define NROWS 16384
#define INF   512
#define HID   256
#define OUTF  16
#define NITER 16
#define SIGMA2 0.1f

// ---------------- scratch (static device globals; no allocation) ----------------
__device__ __nv_bfloat16 g_Lb[(size_t)NROWS * NROWS];          // 512 MB bf16 L
__device__ float         g_h [(size_t)NROWS * HID];            // 16 MB hidden
__device__ float         g_u [2][(size_t)NROWS * OUTF];        // fp32 u ping-pong
__device__ __nv_bfloat16 g_uT[2][(size_t)OUTF * NROWS];        // bf16 u^T ping-pong (B operand)

// ---------------- PTX helpers ----------------
__device__ __forceinline__ uint32_t smem_to_u32(const void* p) {
    uint32_t a;
    asm("{ .reg .u64 t; cvta.to.shared.u64 t, %1; cvt.u32.u64 %0, t; }" : "=r"(a) : "l"(p));
    return a;
}
#define SMEM_SWIZZLE_128B(off) ((off) ^ (((off) >> 3) & 0x70))

__device__ __forceinline__ void cp_async16(uint32_t dst, const void* src) {
    asm volatile("cp.async.cg.shared.global [%0], [%1], 16;" :: "r"(dst), "l"(src) : "memory");
}

#define LDSM_X4(r0_, r1_, r2_, r3_, addr_) \
    asm volatile("ldmatrix.sync.aligned.m8n8.x4.shared.b16 {%0,%1,%2,%3}, [%4];" \
        : "=r"(r0_), "=r"(r1_), "=r"(r2_), "=r"(r3_) : "r"(addr_))

__device__ __forceinline__ void mma16816(float* c, uint32_t a0, uint32_t a1, uint32_t a2,
                                         uint32_t a3, uint32_t b0, uint32_t b1) {
    asm volatile(
        "mma.sync.aligned.m16n8k16.row.col.f32.bf16.bf16.f32 "
        "{%0,%1,%2,%3}, {%4,%5,%6,%7}, {%8,%9}, {%0,%1,%2,%3};"
        : "+f"(c[0]), "+f"(c[1]), "+f"(c[2]), "+f"(c[3])
        : "r"(a0), "r"(a1), "r"(a2), "r"(a3), "r"(b0), "r"(b1));
}

// ---------------- kernel 1: L fp32 -> bf16 ----------------
__global__ void convert_L(const float* __restrict__ L) {
    size_t total4 = (size_t)NROWS * NROWS / 4;
    size_t stride = (size_t)gridDim.x * blockDim.x;
    const float4* L4 = (const float4*)L;
    __nv_bfloat162* out = (__nv_bfloat162*)g_Lb;
    for (size_t i = (size_t)blockIdx.x * blockDim.x + threadIdx.x; i < total4; i += stride) {
        float4 v = L4[i];
        out[i * 2]     = __floats2bfloat162_rn(v.x, v.y);
        out[i * 2 + 1] = __floats2bfloat162_rn(v.z, v.w);
    }
}

// ---------------- kernel 2: h = elu(f @ W1 + b1), fp32 tiled GEMM ----------------
__global__ __launch_bounds__(256) void hidden_kernel(const float* __restrict__ f,
                                                     const float* __restrict__ W1,
                                                     const float* __restrict__ b1) {
    __shared__ float As[16][68];
    __shared__ float Bs[16][68];
    int tx = threadIdx.x, ty = threadIdx.y;
    int tid = ty * 16 + tx;
    int row0 = blockIdx.y * 64;
    int col0 = blockIdx.x * 64;
    float acc[4][4] = {};
    for (int k0 = 0; k0 < INF; k0 += 16) {
        #pragma unroll
        for (int it = 0; it < 4; it++) {
            int r  = (tid >> 4) + it * 16;
            int kk = tid & 15;
            As[kk][r] = f[(size_t)(row0 + r) * INF + k0 + kk];
        }
        #pragma unroll
        for (int it = 0; it < 4; it++) {
            int kk = (tid >> 6) + it * 4;
            int c  = tid & 63;
            Bs[kk][c] = W1[(size_t)(k0 + kk) * HID + col0 + c];
        }
        __syncthreads();
        #pragma unroll
        for (int kk = 0; kk < 16; kk++) {
            float4 a4 = *(const float4*)&As[kk][ty * 4];
            float4 b4 = *(const float4*)&Bs[kk][tx * 4];
            float av[4] = {a4.x, a4.y, a4.z, a4.w};
            float bv[4] = {b4.x, b4.y, b4.z, b4.w};
            #pragma unroll
            for (int i = 0; i < 4; i++)
                #pragma unroll
                for (int j = 0; j < 4; j++)
                    acc[i][j] += av[i] * bv[j];
        }
        __syncthreads();
    }
    #pragma unroll
    for (int i = 0; i < 4; i++) {
        int r = row0 + ty * 4 + i;
        #pragma unroll
        for (int j = 0; j < 4; j++) {
            int c = col0 + tx * 4 + j;
            float v = acc[i][j] + b1[c];
            v = v > 0.0f ? v : expm1f(v);
            g_h[(size_t)r * HID + c] = v;
        }
    }
}

// ---------------- kernel 3: u0 = f@Ws + bs + h@W2 + b2 (also writes bf16 u0^T) ----------------
__global__ __launch_bounds__(256) void u0_kernel(const float* __restrict__ f,
                                                 const float* __restrict__ Ws,
                                                 const float* __restrict__ bs,
                                                 const float* __restrict__ W2,
                                                 const float* __restrict__ b2) {
    __shared__ float sWs[INF * OUTF];   // 32 KB
    __shared__ float sW2[HID * OUTF];   // 16 KB
    int tid = threadIdx.x;
    for (int i = tid; i < INF * OUTF; i += 256) sWs[i] = Ws[i];
    for (int i = tid; i < HID * OUTF; i += 256) sW2[i] = W2[i];
    __syncthreads();
    int c   = tid & 15;
    int row = blockIdx.x * 16 + (tid >> 4);
    float acc = bs[c] + b2[c];
    const float4* f4 = (const float4*)(f + (size_t)row * INF);
    #pragma unroll 4
    for (int k4 = 0; k4 < INF / 4; k4++) {
        float4 v = f4[k4];
        int k = k4 * 4;
        acc += v.x * sWs[k * 16 + c] + v.y * sWs[(k + 1) * 16 + c]
             + v.z * sWs[(k + 2) * 16 + c] + v.w * sWs[(k + 3) * 16 + c];
    }
    const float4* h4 = (const float4*)(g_h + (size_t)row * HID);
    #pragma unroll 4
    for (int k4 = 0; k4 < HID / 4; k4++) {
        float4 v = h4[k4];
        int k = k4 * 4;
        acc += v.x * sW2[k * 16 + c] + v.y * sW2[(k + 1) * 16 + c]
             + v.z * sW2[(k + 2) * 16 + c] + v.w * sW2[(k + 3) * 16 + c];
    }
    g_u[0][(size_t)row * OUTF + c] = acc;
    g_uT[0][(size_t)c * NROWS + row] = __float2bfloat16_rn(acc);
}

// ---------------- kernel 4: one diffusion step, warp-MMA GEMM + fused update ----------------
// Grid 256 CTAs x 128 threads (4 warps). CTA: D[64,16] = Lb[r0:r0+64, :] @ u ; u_new = u - s2*D.
// Per warp: 16 rows, two m16n8k16 accumulators (n = 0..7, 8..15), K = 16384.
#define NSTG 5
#define KCH 64
#define A_BYTES (64 * 128)             // 8 KB per stage (64 rows x 64 k bf16)
#define B_BYTES (16 * 128)             // 2 KB per stage (16 n x 64 k bf16)
#define STG_BYTES (A_BYTES + B_BYTES)  // 10240
#define DIFF_SMEM (NSTG * STG_BYTES)   // 51200
#define NCHUNK (NROWS / KCH)           // 256

__global__ __launch_bounds__(128) void diff_kernel(int sel_in, float* __restrict__ final_out) {
    extern __shared__ char smem[];
    uint32_t sbase = smem_to_u32(smem);
    int tid = threadIdx.x;
    int wid = tid >> 5, lane = tid & 31;
    int r0 = blockIdx.x * 64;

    const __nv_bfloat16* Abase = g_Lb + (size_t)r0 * NROWS;
    const __nv_bfloat16* uT    = g_uT[sel_in];

    // cp.async mapping: A rows (tid>>3)+16i, seg tid&7 ; B row tid>>3, seg tid&7
    const int l_row = tid >> 3;
    const int l_seg = tid & 7;

    auto load_chunk = [&](int j, int s) {
        uint32_t Ab = sbase + (uint32_t)s * STG_BYTES;
        uint32_t Bb = Ab + A_BYTES;
        int k0 = j * KCH;
        #pragma unroll
        for (int i = 0; i < 4; i++) {
            int row = l_row + 16 * i;
            uint32_t off = (uint32_t)(row * 128 + l_seg * 16);
            cp_async16(Ab + SMEM_SWIZZLE_128B(off),
                       Abase + (size_t)row * NROWS + k0 + l_seg * 8);
        }
        uint32_t boff = (uint32_t)(l_row * 128 + l_seg * 16);
        cp_async16(Bb + SMEM_SWIZZLE_128B(boff),
                   uT + (size_t)l_row * NROWS + k0 + l_seg * 8);
    };

    // prologue: fill all stages
    #pragma unroll
    for (int i = 0; i < NSTG; i++) {
        load_chunk(i, i);
        asm volatile("cp.async.commit_group;" ::: "memory");
    }

    // ldmatrix per-thread address roles
    const int a_r = lane & 15;             // row within warp's 16-row tile
    const int a_h = (lane >> 4) * 16;      // +16B for k+8 half
    const int b_n = (lane & 7) + ((lane & 16) ? 8 : 0);
    const int b_h = ((lane >> 3) & 1) * 16;

    float acc0[4] = {0.f, 0.f, 0.f, 0.f};  // n = 0..7
    float acc1[4] = {0.f, 0.f, 0.f, 0.f};  // n = 8..15

    for (int i = 0; i < NCHUNK; i++) {
        int s = i % NSTG;
        asm volatile("cp.async.wait_group 4;" ::: "memory");   // chunk i resident (this thread)
        __syncthreads();                                        // all threads' data visible

        uint32_t Ab = sbase + (uint32_t)s * STG_BYTES;
        uint32_t Bb = Ab + A_BYTES;
        #pragma unroll
        for (int kk = 0; kk < KCH; kk += 16) {
            uint32_t aoff = (uint32_t)((wid * 16 + a_r) * 128 + kk * 2 + a_h);
            uint32_t a0, a1, a2, a3;
            LDSM_X4(a0, a1, a2, a3, Ab + SMEM_SWIZZLE_128B(aoff));
            uint32_t boff = (uint32_t)(b_n * 128 + kk * 2 + b_h);
            uint32_t b0, b1, b2, b3;
            LDSM_X4(b0, b1, b2, b3, Bb + SMEM_SWIZZLE_128B(boff));
            mma16816(acc0, a0, a1, a2, a3, b0, b1);
            mma16816(acc1, a0, a1, a2, a3, b2, b3);
        }
        __syncthreads();                                        // stage s fully consumed

        int j = i + NSTG;
        if (j < NCHUNK) load_chunk(j, s);
        asm volatile("cp.async.commit_group;" ::: "memory");
    }

    // ---- epilogue: u_new = u - sigma2 * D, write fp32 u (or d_out) + bf16 u^T ----
    int gr = lane >> 2;            // 0..7
    int gc = (lane & 3) * 2;       // 0,2,4,6
    int rowA = r0 + wid * 16 + gr;
    int rowB = rowA + 8;

    const float* uA = g_u[sel_in] + (size_t)rowA * OUTF;
    const float* uB = g_u[sel_in] + (size_t)rowB * OUTF;
    float rA[4], rB[4];
    rA[0] = uA[gc]     - SIGMA2 * acc0[0];
    rA[1] = uA[gc + 1] - SIGMA2 * acc0[1];
    rA[2] = uA[gc + 8] - SIGMA2 * acc1[0];
    rA[3] = uA[gc + 9] - SIGMA2 * acc1[1];
    rB[0] = uB[gc]     - SIGMA2 * acc0[2];
    rB[1] = uB[gc + 1] - SIGMA2 * acc0[3];
    rB[2] = uB[gc + 8] - SIGMA2 * acc1[2];
    rB[3] = uB[gc + 9] - SIGMA2 * acc1[3];

    if (final_out) {
        *(float2*)(final_out + (size_t)rowA * OUTF + gc)     = make_float2(rA[0], rA[1]);
        *(float2*)(final_out + (size_t)rowA * OUTF + gc + 8) = make_float2(rA[2], rA[3]);
        *(float2*)(final_out + (size_t)rowB * OUTF + gc)     = make_float2(rB[0], rB[1]);
        *(float2*)(final_out + (size_t)rowB * OUTF + gc + 8) = make_float2(rB[2], rB[3]);
    } else {
        int so = sel_in ^ 1;
        float* uo = g_u[so];
        *(float2*)(uo + (size_t)rowA * OUTF + gc)     = make_float2(rA[0], rA[1]);
        *(float2*)(uo + (size_t)rowA * OUTF + gc + 8) = make_float2(rA[2], rA[3]);
        *(float2*)(uo + (size_t)rowB * OUTF + gc)     = make_float2(rB[0], rB[1]);
        *(float2*)(uo + (size_t)rowB * OUTF + gc + 8) = make_float2(rB[2], rB[3]);
        __nv_bfloat16* t = g_uT[so];
        t[(size_t)(gc)     * NROWS + rowA] = __float2bfloat16_rn(rA[0]);
        t[(size_t)(gc + 1) * NROWS + rowA] = __float2bfloat16_rn(rA[1]);
        t[(size_t)(gc + 8) * NROWS + rowA] = __float2bfloat16_rn(rA[2]);
        t[(size_t)(gc + 9) * NROWS + rowA] = __float2bfloat16_rn(rA[3]);
        t[(size_t)(gc)     * NROWS + rowB] = __float2bfloat16_rn(rB[0]);
        t[(size_t)(gc + 1) * NROWS + rowB] = __float2bfloat16_rn(rB[1]);
        t[(size_t)(gc + 8) * NROWS + rowB] = __float2bfloat16_rn(rB[2]);
        t[(size_t)(gc + 9) * NROWS + rowB] = __float2bfloat16_rn(rB[3]);
    }
}

// ---------------- launch ----------------
extern "C" void kernel_launch(void* const* d_in, const int* in_sizes, int n_in,
                              void* d_out, int out_size) {
    const float* f  = (const float*)d_in[0];
    const float* L  = (const float*)d_in[1];
    const float* W1 = (const float*)d_in[2];
    const float* b1 = (const float*)d_in[3];
    const float* W2 = (const float*)d_in[4];
    const float* b2 = (const float*)d_in[5];
    const float* Ws = (const float*)d_in[6];
    const float* bs = (const float*)d_in[7];
    float* out = (float*)d_out;
    (void)in_sizes; (void)n_in; (void)out_size;

    convert_L<<<8192, 256>>>(L);
    hidden_kernel<<<dim3(HID / 64, NROWS / 64), dim3(16, 16)>>>(f, W1, b1);
    u0_kernel<<<NROWS / 16, 256>>>(f, Ws, bs, W2, b2);

    static int smem_set = 0;
    if (!smem_set) {
        cudaFuncSetAttribute(diff_kernel, cudaFuncAttributeMaxDynamicSharedMemorySize, DIFF_SMEM);
        smem_set = 1;
    }
    int sel = 0;
    for (int it = 0; it < NITER; it++) {
        float* fo = (it == NITER - 1) ? out : nullptr;
        diff_kernel<<<NROWS / 64, 128, DIFF_SMEM>>>(sel, fo);
        sel ^= 1;
    }
}